// round 8
// baseline (speedup 1.0000x reference)
#include <cuda_runtime.h>
#include <math.h>

#define NB 8192
#define NSLICE 37              // 4 x-blocks * 37 slices = 148 blocks = 1 block/SM
#define PSTRIDE 38             // padded partial stride (19 float4 per row); pad slot stays 0
#define RPT 4                  // rows per thread in attention
#define RSTRIDE (NB / RPT)     // 2048
#define NPAIR (RPT / 2)        // 2 packed row-pairs
#define JMAX 222               // max j per slice (ceil(8192/37))
#define LOG2E 1.4426950408889634f

typedef unsigned long long u64;

// ---- scratch (device globals; no allocation allowed) ----
__device__ float4      gQ4[NB];        // q * (0.5*log2e) per row
__device__ float       gM[NB];         // -(|q_tilde| * kbound) per row
__device__ ulonglong2  gKDxy[NB];      // {pack(kx,kx), pack(ky,ky)}
__device__ ulonglong2  gKDzw[NB];      // {pack(kz,kz), pack(kw,kw)}
__device__ u64         gCCd[NB];       // pack(c,c), c = x . conv_w
__device__ float4      gP[NB * PSTRIDE / 2];  // {sum,y} float2 pairs, padded; pad stays 0

__device__ __forceinline__ u64 ffma2(u64 a, u64 b, u64 c) {
    u64 d;
    asm("fma.rn.f32x2 %0, %1, %2, %3;" : "=l"(d) : "l"(a), "l"(b), "l"(c));
    return d;
}
__device__ __forceinline__ u64 fadd2(u64 a, u64 b) {
    u64 d;
    asm("add.rn.f32x2 %0, %1, %2;" : "=l"(d) : "l"(a), "l"(b));
    return d;
}
__device__ __forceinline__ u64 pack2(float lo, float hi) {
    u64 d;
    asm("mov.b64 %0, {%1, %2};" : "=l"(d) : "f"(lo), "f"(hi));
    return d;
}
__device__ __forceinline__ void unpack2(u64 v, float& lo, float& hi) {
    asm("mov.b64 {%0, %1}, %2;" : "=f"(lo), "=f"(hi) : "l"(v));
}
// packed exp2 via one f16x2 MUFU op: args are in [-~20, 0] (normal fp16 range
// for this data: scores bounded by ~10), dominant weights ~0.1% quantization.
__device__ __forceinline__ u64 exp2_pair(u64 s) {
    u64 e;
    asm("{\n\t"
        ".reg .f32 s0, s1, e0, e1;\n\t"
        ".reg .b32 hp;\n\t"
        ".reg .b16 l16, h16;\n\t"
        "mov.b64 {s0, s1}, %1;\n\t"
        "cvt.rn.f16x2.f32 hp, s1, s0;\n\t"   // first src -> high half => hi=s1, lo=s0
        "ex2.approx.f16x2 hp, hp;\n\t"
        "mov.b32 {l16, h16}, hp;\n\t"
        "cvt.f32.f16 e0, l16;\n\t"
        "cvt.f32.f16 e1, h16;\n\t"
        "mov.b64 %0, {e0, e1};\n\t"
        "}" : "=l"(e) : "l"(s));
    return e;
}
// hardware tanh (single MUFU op, max rel err ~2^-10.7)
__device__ __forceinline__ float tanh_hw(float x) {
    float y;
    asm("tanh.approx.f32 %0, %1;" : "=f"(y) : "f"(x));
    return y;
}

// ---- smem weight layout (float offsets); all 16B-aligned where vectorized ----
#define O_WFM   0      // 8x16
#define O_BFM   128
#define O_WC1   144    // 16x16
#define O_BC1   400
#define O_WP1   416    // 16x12
#define O_BP1   608
#define O_WC2   620    // 12x8
#define O_BC2   716
#define O_WP2   724    // 8x4
#define O_BP2   756
#define O_WC3   760    // 4x4
#define O_BC3   776
#define O_ROT   780
#define O_ENT   796
#define O_CW    812
#define SM_FLOATS 816

// 4-lane cooperative layer: lane q computes outputs [q*NO/4, (q+1)*NO/4),
// weights loaded vectorized, full activation re-assembled via width-4 shuffles.
template<int NI, int NO>
__device__ __forceinline__ void layer4(const float* __restrict__ smw, int woff, int boff,
                                       int q, const float* __restrict__ xin,
                                       float* __restrict__ xout_full)
{
    constexpr int NOq = NO / 4;
    float acc[NOq];
    #pragma unroll
    for (int oo = 0; oo < NOq; oo++) acc[oo] = smw[boff + q * NOq + oo];
    #pragma unroll
    for (int i = 0; i < NI; i++) {
        float xi = xin[i];
        if constexpr (NOq == 4) {
            float4 w = *reinterpret_cast<const float4*>(smw + woff + i * NO + q * 4);
            acc[0] = fmaf(xi, w.x, acc[0]);
            acc[1] = fmaf(xi, w.y, acc[1]);
            acc[2] = fmaf(xi, w.z, acc[2]);
            acc[3] = fmaf(xi, w.w, acc[3]);
        } else if constexpr (NOq == 2) {
            float2 w = *reinterpret_cast<const float2*>(smw + woff + i * NO + q * 2);
            acc[0] = fmaf(xi, w.x, acc[0]);
            acc[1] = fmaf(xi, w.y, acc[1]);
        } else {
            #pragma unroll
            for (int oo = 0; oo < NOq; oo++)
                acc[oo] = fmaf(xi, smw[woff + i * NO + q * NOq + oo], acc[oo]);
        }
    }
    float loc[NOq];
    #pragma unroll
    for (int oo = 0; oo < NOq; oo++) loc[oo] = tanh_hw(acc[oo]);
    #pragma unroll
    for (int i = 0; i < NO; i++)
        xout_full[i] = __shfl_sync(0xffffffffu, loc[i % NOq], i / NOq, 4);
}

__device__ __forceinline__ void stage(float* dst, const float* src, int n, int tid, int nthr) {
    for (int i = tid; i < n; i += nthr) dst[i] = src[i];
}

// ---------- Kernel A: MLP chain, 4 lanes per row ----------
__global__ void __launch_bounds__(256) k_prep(
                       const float* __restrict__ inp,
                       const float* __restrict__ Wfm, const float* __restrict__ bfm,
                       const float* __restrict__ Wc1, const float* __restrict__ bc1,
                       const float* __restrict__ Wp1, const float* __restrict__ bp1,
                       const float* __restrict__ Wc2, const float* __restrict__ bc2,
                       const float* __restrict__ Wp2, const float* __restrict__ bp2,
                       const float* __restrict__ Wc3, const float* __restrict__ bc3,
                       const float* __restrict__ rot, const float* __restrict__ ent,
                       const float* __restrict__ conv_w)
{
    __shared__ __align__(16) float sm[SM_FLOATS];
    int tid = threadIdx.x;
    stage(sm + O_WFM, Wfm, 128, tid, 256);
    stage(sm + O_BFM, bfm, 16,  tid, 256);
    stage(sm + O_WC1, Wc1, 256, tid, 256);
    stage(sm + O_BC1, bc1, 16,  tid, 256);
    stage(sm + O_WP1, Wp1, 192, tid, 256);
    stage(sm + O_BP1, bp1, 12,  tid, 256);
    stage(sm + O_WC2, Wc2, 96,  tid, 256);
    stage(sm + O_BC2, bc2, 8,   tid, 256);
    stage(sm + O_WP2, Wp2, 32,  tid, 256);
    stage(sm + O_BP2, bp2, 4,   tid, 256);
    stage(sm + O_WC3, Wc3, 16,  tid, 256);
    stage(sm + O_BC3, bc3, 4,   tid, 256);
    stage(sm + O_ROT, rot, 16,  tid, 256);
    stage(sm + O_ENT, ent, 16,  tid, 256);
    stage(sm + O_CW,  conv_w, 4, tid, 256);
    __syncthreads();

    int r = blockIdx.x * 64 + (tid >> 2);   // row
    int q = tid & 3;                        // lane within row

    float x0[16], x1[16];
    {
        const float4* ip = reinterpret_cast<const float4*>(inp + r * 8);
        float4 v0 = __ldg(ip), v1 = __ldg(ip + 1);
        x0[0]=v0.x; x0[1]=v0.y; x0[2]=v0.z; x0[3]=v0.w;
        x0[4]=v1.x; x0[5]=v1.y; x0[6]=v1.z; x0[7]=v1.w;
    }

    layer4<8, 16>(sm, O_WFM, O_BFM, q, x0, x1);
    layer4<16,16>(sm, O_WC1, O_BC1, q, x1, x0);
    layer4<16,12>(sm, O_WP1, O_BP1, q, x0, x1);
    layer4<12, 8>(sm, O_WC2, O_BC2, q, x1, x0);
    layer4<8,  4>(sm, O_WP2, O_BP2, q, x0, x1);
    layer4<4,  4>(sm, O_WC3, O_BC3, q, x1, x0);   // final x in x0[0..3]

    if (q == 0) {
        float qv[4], kv[4];
        #pragma unroll
        for (int c = 0; c < 4; c++) {
            float sq = 0.f, sk = 0.f;
            #pragma unroll
            for (int i = 0; i < 4; i++) {
                sq = fmaf(x0[i], sm[O_ROT + i * 4 + c], sq);
                sk = fmaf(x0[i], sm[O_ENT + i * 4 + c], sk);
            }
            qv[c] = sq * (0.5f * LOG2E);
            kv[c] = sk;
        }

        // analytic bound: |x_i| <= 1 (tanh) => |k_c| <= sum_i |ent[i][c]|
        float A2 = 0.f;
        #pragma unroll
        for (int c = 0; c < 4; c++) {
            float ac = 0.f;
            #pragma unroll
            for (int i = 0; i < 4; i++) ac += fabsf(sm[O_ENT + i * 4 + c]);
            A2 = fmaf(ac, ac, A2);
        }

        gQ4[r] = make_float4(qv[0], qv[1], qv[2], qv[3]);
        float qn = sqrtf(qv[0]*qv[0] + qv[1]*qv[1] + qv[2]*qv[2] + qv[3]*qv[3]);
        gM[r] = -(qn * sqrtf(A2));
        ulonglong2 kxy, kzw;
        kxy.x = pack2(kv[0], kv[0]);
        kxy.y = pack2(kv[1], kv[1]);
        kzw.x = pack2(kv[2], kv[2]);
        kzw.y = pack2(kv[3], kv[3]);
        gKDxy[r] = kxy;
        gKDzw[r] = kzw;
        float cc = fmaf(x0[0], sm[O_CW+0], fmaf(x0[1], sm[O_CW+1],
                   fmaf(x0[2], sm[O_CW+2], x0[3] * sm[O_CW+3])));
        gCCd[r] = pack2(cc, cc);
    }
}

// ---------- Kernel B: streaming attention, f32x2-packed dot + f16x2 exp2 ----------
__global__ void __launch_bounds__(512) k_attn() {
    __shared__ ulonglong2 smKxy[JMAX];
    __shared__ ulonglong2 smKzw[JMAX];
    __shared__ u64        smCc[JMAX];

    int tid   = threadIdx.x;
    int t     = blockIdx.x * 512 + tid;   // 0..RSTRIDE-1
    int slice = blockIdx.y;

    int j0  = (slice * NB) / NSLICE;
    int cnt = ((slice + 1) * NB) / NSLICE - j0;

    if (tid < cnt) {
        smKxy[tid] = gKDxy[j0 + tid];
        smKzw[tid] = gKDzw[j0 + tid];
        smCc[tid]  = gCCd[j0 + tid];
    }

    u64 qx[NPAIR], qy[NPAIR], qz[NPAIR], qw[NPAIR];
    u64 nm[NPAIR], sum[NPAIR], yy[NPAIR];

    #pragma unroll
    for (int p = 0; p < NPAIR; p++) {
        int r0 = t + (2 * p)     * RSTRIDE;
        int r1 = t + (2 * p + 1) * RSTRIDE;
        float4 qa = gQ4[r0];
        float4 qb = gQ4[r1];
        qx[p] = pack2(qa.x, qb.x);
        qy[p] = pack2(qa.y, qb.y);
        qz[p] = pack2(qa.z, qb.z);
        qw[p] = pack2(qa.w, qb.w);
        nm[p] = pack2(gM[r0], gM[r1]);
        sum[p] = pack2(0.f, 0.f);
        yy[p]  = pack2(0.f, 0.f);
    }

    __syncthreads();

    #pragma unroll 4
    for (int j = 0; j < cnt; j++) {
        ulonglong2 kxy = smKxy[j];
        ulonglong2 kzw = smKzw[j];
        u64        cc  = smCc[j];
        #pragma unroll
        for (int p = 0; p < NPAIR; p++) {
            u64 s = ffma2(qx[p], kxy.x, nm[p]);
            s = ffma2(qy[p], kxy.y, s);
            s = ffma2(qz[p], kzw.x, s);
            s = ffma2(qw[p], kzw.y, s);
            u64 e = exp2_pair(s);
            sum[p] = fadd2(sum[p], e);
            yy[p]  = ffma2(e, cc, yy[p]);
        }
    }

    float2* __restrict__ gp2 = reinterpret_cast<float2*>(gP);
    #pragma unroll
    for (int p = 0; p < NPAIR; p++) {
        float s0, s1, y0, y1;
        unpack2(sum[p], s0, s1);
        unpack2(yy[p],  y0, y1);
        int r0 = t + (2 * p)     * RSTRIDE;
        int r1 = t + (2 * p + 1) * RSTRIDE;
        gp2[r0 * PSTRIDE + slice] = make_float2(s0, y0);
        gp2[r1 * PSTRIDE + slice] = make_float2(s1, y1);
    }
}

// ---------- Kernel C: reduce slices (4 lanes/row) + conv-sigmoid + head-sigmoid ----------
__global__ void __launch_bounds__(256) k_tail(
                       const float* __restrict__ conv_b,
                       const float* __restrict__ head_w, const float* __restrict__ head_b,
                       float* __restrict__ out)
{
    int tid = blockIdx.x * 256 + threadIdx.x;
    int row = tid >> 2;          // 4 lanes per row
    int l   = tid & 3;

    const float4* __restrict__ p = gP + row * (PSTRIDE / 2);
    float sum = 0.f, y = 0.f;
    #pragma unroll
    for (int i = l; i < PSTRIDE / 2; i += 4) {
        float4 v = __ldg(p + i);      // {sum0, y0, sum1, y1}
        sum += v.x + v.z;
        y   += v.y + v.w;
    }
    sum += __shfl_xor_sync(0xffffffffu, sum, 1, 4);
    y   += __shfl_xor_sync(0xffffffffu, y,   1, 4);
    sum += __shfl_xor_sync(0xffffffffu, sum, 2, 4);
    y   += __shfl_xor_sync(0xffffffffu, y,   2, 4);

    if (l == 0) {
        float z = fmaf(y, 1.f / sum, conv_b[0]);
        float f = 1.f / (1.f + expf(-z));
        float logit = fmaf(f, head_w[0], head_b[0]);
        out[row] = 1.f / (1.f + expf(-logit));
    }
}

extern "C" void kernel_launch(void* const* d_in, const int* in_sizes, int n_in,
                              void* d_out, int out_size)
{
    const float* inp  = (const float*)d_in[0];
    const float* Wfm  = (const float*)d_in[1];
    const float* bfm  = (const float*)d_in[2];
    const float* Wc1  = (const float*)d_in[3];
    const float* bc1  = (const float*)d_in[4];
    const float* Wp1  = (const float*)d_in[5];
    const float* bp1  = (const float*)d_in[6];
    const float* Wc2  = (const float*)d_in[7];
    const float* bc2  = (const float*)d_in[8];
    const float* Wp2  = (const float*)d_in[9];
    const float* bp2  = (const float*)d_in[10];
    const float* Wc3  = (const float*)d_in[11];
    const float* bc3  = (const float*)d_in[12];
    const float* rot  = (const float*)d_in[13];
    const float* ent  = (const float*)d_in[14];
    const float* cw   = (const float*)d_in[15];
    const float* cb   = (const float*)d_in[16];
    const float* hw   = (const float*)d_in[17];
    const float* hb   = (const float*)d_in[18];
    float* out = (float*)d_out;

    k_prep<<<NB / 64, 256>>>(inp, Wfm, bfm, Wc1, bc1, Wp1, bp1,
                             Wc2, bc2, Wp2, bp2, Wc3, bc3, rot, ent, cw);
    dim3 gridB(RSTRIDE / 512, NSLICE);   // 4 x 37 = 148 blocks, 16 warps each
    k_attn<<<gridB, 512>>>();
    k_tail<<<NB * 4 / 256, 256>>>(cb, hw, hb, out);
}

// round 10
// speedup vs baseline: 1.1633x; 1.1633x over previous
#include <cuda_runtime.h>
#include <cuda_fp16.h>
#include <math.h>

#define NB 8192
#define NSLICE 37              // 4 x-blocks * 37 slices = 148 blocks = 1 block/SM
#define PSTRIDE 38             // padded partial stride; pad slot stays 0
#define RPT 4                  // rows per thread in attention
#define RSTRIDE (NB / RPT)     // 2048
#define NPAIR (RPT / 2)        // 2 packed row-pairs
#define JMAX 222               // max j per slice
#define NPREPB 128             // prep blocks (64 rows each)
#define LOG2E 1.4426950408889634f

typedef unsigned int u32;

// ---- scratch (device globals; no allocation allowed) ----
__device__ float4 gQ4[NB];                 // q * (0.5*log2e) per row (fp32)
__device__ float  gQn[NB];                 // |q_tilde| per row
__device__ uint4  gKh[NB];                 // {h2(kx,kx), h2(ky,ky), h2(kz,kz), h2(kw,kw)}
__device__ u32    gCh[NB];                 // h2(c,c), c = x . conv_w
__device__ __align__(16) float gKmaxBlk[NPREPB];  // per-prep-block max |k|
__device__ float4 gP[NB * PSTRIDE / 2];    // {sum,y} float2 pairs, padded

__device__ __forceinline__ __half2 u2h(u32 v) { __half2 h; *reinterpret_cast<u32*>(&h) = v; return h; }
__device__ __forceinline__ u32 h2u(__half2 h) { return *reinterpret_cast<u32*>(&h); }
__device__ __forceinline__ __half2 hexp2_x(__half2 v) {
    u32 r, s = h2u(v);
    asm("ex2.approx.f16x2 %0, %1;" : "=r"(r) : "r"(s));
    return u2h(r);
}
// hardware tanh (single MUFU op)
__device__ __forceinline__ float tanh_hw(float x) {
    float y;
    asm("tanh.approx.f32 %0, %1;" : "=f"(y) : "f"(x));
    return y;
}

// ---- smem weight layout (float offsets) ----
#define O_WFM   0
#define O_BFM   128
#define O_WC1   144
#define O_BC1   400
#define O_WP1   416
#define O_BP1   608
#define O_WC2   620
#define O_BC2   716
#define O_WP2   724
#define O_BP2   756
#define O_WC3   760
#define O_BC3   776
#define O_ROT   780
#define O_ENT   796
#define O_CW    812
#define SM_FLOATS 816

template<int NI, int NO>
__device__ __forceinline__ void layer4(const float* __restrict__ smw, int woff, int boff,
                                       int q, const float* __restrict__ xin,
                                       float* __restrict__ xout_full)
{
    constexpr int NOq = NO / 4;
    float acc[NOq];
    #pragma unroll
    for (int oo = 0; oo < NOq; oo++) acc[oo] = smw[boff + q * NOq + oo];
    #pragma unroll
    for (int i = 0; i < NI; i++) {
        float xi = xin[i];
        if constexpr (NOq == 4) {
            float4 w = *reinterpret_cast<const float4*>(smw + woff + i * NO + q * 4);
            acc[0] = fmaf(xi, w.x, acc[0]);
            acc[1] = fmaf(xi, w.y, acc[1]);
            acc[2] = fmaf(xi, w.z, acc[2]);
            acc[3] = fmaf(xi, w.w, acc[3]);
        } else if constexpr (NOq == 2) {
            float2 w = *reinterpret_cast<const float2*>(smw + woff + i * NO + q * 2);
            acc[0] = fmaf(xi, w.x, acc[0]);
            acc[1] = fmaf(xi, w.y, acc[1]);
        } else {
            #pragma unroll
            for (int oo = 0; oo < NOq; oo++)
                acc[oo] = fmaf(xi, smw[woff + i * NO + q * NOq + oo], acc[oo]);
        }
    }
    float loc[NOq];
    #pragma unroll
    for (int oo = 0; oo < NOq; oo++) loc[oo] = tanh_hw(acc[oo]);
    #pragma unroll
    for (int i = 0; i < NO; i++)
        xout_full[i] = __shfl_sync(0xffffffffu, loc[i % NOq], i / NOq, 4);
}

__device__ __forceinline__ void stage(float* dst, const float* src, int n, int tid, int nthr) {
    for (int i = tid; i < n; i += nthr) dst[i] = src[i];
}

// ---------- Kernel A: MLP chain, 4 lanes per row; emits fp16 k/c + block kmax ----------
__global__ void __launch_bounds__(256) k_prep(
                       const float* __restrict__ inp,
                       const float* __restrict__ Wfm, const float* __restrict__ bfm,
                       const float* __restrict__ Wc1, const float* __restrict__ bc1,
                       const float* __restrict__ Wp1, const float* __restrict__ bp1,
                       const float* __restrict__ Wc2, const float* __restrict__ bc2,
                       const float* __restrict__ Wp2, const float* __restrict__ bp2,
                       const float* __restrict__ Wc3, const float* __restrict__ bc3,
                       const float* __restrict__ rot, const float* __restrict__ ent,
                       const float* __restrict__ conv_w)
{
    __shared__ __align__(16) float sm[SM_FLOATS];
    __shared__ float smKn[64];
    int tid = threadIdx.x;
    stage(sm + O_WFM, Wfm, 128, tid, 256);
    stage(sm + O_BFM, bfm, 16,  tid, 256);
    stage(sm + O_WC1, Wc1, 256, tid, 256);
    stage(sm + O_BC1, bc1, 16,  tid, 256);
    stage(sm + O_WP1, Wp1, 192, tid, 256);
    stage(sm + O_BP1, bp1, 12,  tid, 256);
    stage(sm + O_WC2, Wc2, 96,  tid, 256);
    stage(sm + O_BC2, bc2, 8,   tid, 256);
    stage(sm + O_WP2, Wp2, 32,  tid, 256);
    stage(sm + O_BP2, bp2, 4,   tid, 256);
    stage(sm + O_WC3, Wc3, 16,  tid, 256);
    stage(sm + O_BC3, bc3, 4,   tid, 256);
    stage(sm + O_ROT, rot, 16,  tid, 256);
    stage(sm + O_ENT, ent, 16,  tid, 256);
    stage(sm + O_CW,  conv_w, 4, tid, 256);
    __syncthreads();

    int r = blockIdx.x * 64 + (tid >> 2);   // row
    int q = tid & 3;                        // lane within row

    float x0[16], x1[16];
    {
        const float4* ip = reinterpret_cast<const float4*>(inp + r * 8);
        float4 v0 = __ldg(ip), v1 = __ldg(ip + 1);
        x0[0]=v0.x; x0[1]=v0.y; x0[2]=v0.z; x0[3]=v0.w;
        x0[4]=v1.x; x0[5]=v1.y; x0[6]=v1.z; x0[7]=v1.w;
    }

    layer4<8, 16>(sm, O_WFM, O_BFM, q, x0, x1);
    layer4<16,16>(sm, O_WC1, O_BC1, q, x1, x0);
    layer4<16,12>(sm, O_WP1, O_BP1, q, x0, x1);
    layer4<12, 8>(sm, O_WC2, O_BC2, q, x1, x0);
    layer4<8,  4>(sm, O_WP2, O_BP2, q, x0, x1);
    layer4<4,  4>(sm, O_WC3, O_BC3, q, x1, x0);   // final x in x0[0..3]

    if (q == 0) {
        float qv[4], kv[4];
        #pragma unroll
        for (int c = 0; c < 4; c++) {
            float sq = 0.f, sk = 0.f;
            #pragma unroll
            for (int i = 0; i < 4; i++) {
                sq = fmaf(x0[i], sm[O_ROT + i * 4 + c], sq);
                sk = fmaf(x0[i], sm[O_ENT + i * 4 + c], sk);
            }
            qv[c] = sq * (0.5f * LOG2E);
            kv[c] = sk;
        }

        gQ4[r] = make_float4(qv[0], qv[1], qv[2], qv[3]);
        float qn = sqrtf(qv[0]*qv[0] + qv[1]*qv[1] + qv[2]*qv[2] + qv[3]*qv[3]);
        gQn[r] = qn;
        float kn = sqrtf(kv[0]*kv[0] + kv[1]*kv[1] + kv[2]*kv[2] + kv[3]*kv[3]);
        smKn[tid >> 2] = kn;

        uint4 kk;
        kk.x = h2u(__floats2half2_rn(kv[0], kv[0]));
        kk.y = h2u(__floats2half2_rn(kv[1], kv[1]));
        kk.z = h2u(__floats2half2_rn(kv[2], kv[2]));
        kk.w = h2u(__floats2half2_rn(kv[3], kv[3]));
        gKh[r] = kk;
        float cc = fmaf(x0[0], sm[O_CW+0], fmaf(x0[1], sm[O_CW+1],
                   fmaf(x0[2], sm[O_CW+2], x0[3] * sm[O_CW+3])));
        gCh[r] = h2u(__floats2half2_rn(cc, cc));
    }
    __syncthreads();
    if (tid == 0) {
        float m = smKn[0];
        #pragma unroll
        for (int i = 1; i < 64; i++) m = fmaxf(m, smKn[i]);
        gKmaxBlk[blockIdx.x] = m;
    }
}

// ---------- Kernel B: streaming attention, full-fp16 inner loop ----------
// per-row offset m = |q_tilde| * max_j|k_j| (exact kmax -> small gap, fp16-safe);
// fp16 accumulators flushed to fp32 every 8 j's; slice partials add exactly.
__global__ void __launch_bounds__(512) k_attn() {
    __shared__ uint4 smK[JMAX];
    __shared__ u32   smC[JMAX];

    int tid   = threadIdx.x;
    int t     = blockIdx.x * 512 + tid;   // 0..RSTRIDE-1
    int slice = blockIdx.y;

    int j0  = (slice * NB) / NSLICE;
    int cnt = ((slice + 1) * NB) / NSLICE - j0;

    if (tid < cnt) {
        smK[tid] = gKh[j0 + tid];
        smC[tid] = gCh[j0 + tid];
    }

    // exact global kmax from per-block maxima (broadcast loads, one-time)
    float kmax = 0.f;
    {
        const float4* km4 = reinterpret_cast<const float4*>(gKmaxBlk);
        #pragma unroll
        for (int i = 0; i < NPREPB / 4; i++) {
            float4 v = __ldg(km4 + i);
            kmax = fmaxf(kmax, fmaxf(fmaxf(v.x, v.y), fmaxf(v.z, v.w)));
        }
    }

    __half2 qx[NPAIR], qy[NPAIR], qz[NPAIR], qw[NPAIR], nmh[NPAIR];
    float sA[NPAIR], sB[NPAIR], yA[NPAIR], yB[NPAIR];

    #pragma unroll
    for (int p = 0; p < NPAIR; p++) {
        int r0 = t + (2 * p)     * RSTRIDE;
        int r1 = t + (2 * p + 1) * RSTRIDE;
        float4 qa = gQ4[r0];
        float4 qb = gQ4[r1];
        qx[p] = __floats2half2_rn(qa.x, qb.x);
        qy[p] = __floats2half2_rn(qa.y, qb.y);
        qz[p] = __floats2half2_rn(qa.z, qb.z);
        qw[p] = __floats2half2_rn(qa.w, qb.w);
        nmh[p] = __floats2half2_rn(-gQn[r0] * kmax, -gQn[r1] * kmax);
        sA[p] = 0.f; sB[p] = 0.f; yA[p] = 0.f; yB[p] = 0.f;
    }

    __syncthreads();

    const __half2 hz = __float2half2_rn(0.f);
    int nfull = cnt >> 3;

    for (int c8 = 0; c8 < nfull; c8++) {
        __half2 sh[NPAIR], yh[NPAIR];
        #pragma unroll
        for (int p = 0; p < NPAIR; p++) { sh[p] = hz; yh[p] = hz; }
        int base = c8 * 8;
        #pragma unroll
        for (int u = 0; u < 8; u++) {
            uint4 kk = smK[base + u];
            __half2 kx = u2h(kk.x), ky = u2h(kk.y), kz = u2h(kk.z), kw = u2h(kk.w);
            __half2 ch = u2h(smC[base + u]);
            #pragma unroll
            for (int p = 0; p < NPAIR; p++) {
                __half2 s = __hfma2(qx[p], kx, nmh[p]);
                s = __hfma2(qy[p], ky, s);
                s = __hfma2(qz[p], kz, s);
                s = __hfma2(qw[p], kw, s);
                __half2 e = hexp2_x(s);
                sh[p] = __hadd2(sh[p], e);
                yh[p] = __hfma2(e, ch, yh[p]);
            }
        }
        #pragma unroll
        for (int p = 0; p < NPAIR; p++) {
            sA[p] += __low2float(sh[p]);  sB[p] += __high2float(sh[p]);
            yA[p] += __low2float(yh[p]);  yB[p] += __high2float(yh[p]);
        }
    }
    // remainder
    {
        __half2 sh[NPAIR], yh[NPAIR];
        #pragma unroll
        for (int p = 0; p < NPAIR; p++) { sh[p] = hz; yh[p] = hz; }
        for (int j = nfull * 8; j < cnt; j++) {
            uint4 kk = smK[j];
            __half2 kx = u2h(kk.x), ky = u2h(kk.y), kz = u2h(kk.z), kw = u2h(kk.w);
            __half2 ch = u2h(smC[j]);
            #pragma unroll
            for (int p = 0; p < NPAIR; p++) {
                __half2 s = __hfma2(qx[p], kx, nmh[p]);
                s = __hfma2(qy[p], ky, s);
                s = __hfma2(qz[p], kz, s);
                s = __hfma2(qw[p], kw, s);
                __half2 e = hexp2_x(s);
                sh[p] = __hadd2(sh[p], e);
                yh[p] = __hfma2(e, ch, yh[p]);
            }
        }
        #pragma unroll
        for (int p = 0; p < NPAIR; p++) {
            sA[p] += __low2float(sh[p]);  sB[p] += __high2float(sh[p]);
            yA[p] += __low2float(yh[p]);  yB[p] += __high2float(yh[p]);
        }
    }

    float2* __restrict__ gp2 = reinterpret_cast<float2*>(gP);
    #pragma unroll
    for (int p = 0; p < NPAIR; p++) {
        int r0 = t + (2 * p)     * RSTRIDE;
        int r1 = t + (2 * p + 1) * RSTRIDE;
        gp2[r0 * PSTRIDE + slice] = make_float2(sA[p], yA[p]);
        gp2[r1 * PSTRIDE + slice] = make_float2(sB[p], yB[p]);
    }
}

// ---------- Kernel C: reduce slices (4 lanes/row) + conv-sigmoid + head-sigmoid ----------
__global__ void __launch_bounds__(256) k_tail(
                       const float* __restrict__ conv_b,
                       const float* __restrict__ head_w, const float* __restrict__ head_b,
                       float* __restrict__ out)
{
    int tid = blockIdx.x * 256 + threadIdx.x;
    int row = tid >> 2;          // 4 lanes per row
    int l   = tid & 3;

    const float4* __restrict__ p = gP + row * (PSTRIDE / 2);
    float sum = 0.f, y = 0.f;
    #pragma unroll
    for (int i = l; i < PSTRIDE / 2; i += 4) {
        float4 v = __ldg(p + i);      // {sum0, y0, sum1, y1}
        sum += v.x + v.z;
        y   += v.y + v.w;
    }
    sum += __shfl_xor_sync(0xffffffffu, sum, 1, 4);
    y   += __shfl_xor_sync(0xffffffffu, y,   1, 4);
    sum += __shfl_xor_sync(0xffffffffu, sum, 2, 4);
    y   += __shfl_xor_sync(0xffffffffu, y,   2, 4);

    if (l == 0) {
        float z = fmaf(y, 1.f / sum, conv_b[0]);
        float f = 1.f / (1.f + expf(-z));
        float logit = fmaf(f, head_w[0], head_b[0]);
        out[row] = 1.f / (1.f + expf(-logit));
    }
}

extern "C" void kernel_launch(void* const* d_in, const int* in_sizes, int n_in,
                              void* d_out, int out_size)
{
    const float* inp  = (const float*)d_in[0];
    const float* Wfm  = (const float*)d_in[1];
    const float* bfm  = (const float*)d_in[2];
    const float* Wc1  = (const float*)d_in[3];
    const float* bc1  = (const float*)d_in[4];
    const float* Wp1  = (const float*)d_in[5];
    const float* bp1  = (const float*)d_in[6];
    const float* Wc2  = (const float*)d_in[7];
    const float* bc2  = (const float*)d_in[8];
    const float* Wp2  = (const float*)d_in[9];
    const float* bp2  = (const float*)d_in[10];
    const float* Wc3  = (const float*)d_in[11];
    const float* bc3  = (const float*)d_in[12];
    const float* rot  = (const float*)d_in[13];
    const float* ent  = (const float*)d_in[14];
    const float* cw   = (const float*)d_in[15];
    const float* cb   = (const float*)d_in[16];
    const float* hw   = (const float*)d_in[17];
    const float* hb   = (const float*)d_in[18];
    float* out = (float*)d_out;

    k_prep<<<NPREPB, 256>>>(inp, Wfm, bfm, Wc1, bc1, Wp1, bp1,
                            Wc2, bc2, Wp2, bp2, Wc3, bc3, rot, ent, cw);
    dim3 gridB(RSTRIDE / 512, NSLICE);   // 4 x 37 = 148 blocks, 16 warps each
    k_attn<<<gridB, 512>>>();
    k_tail<<<NB * 4 / 256, 256>>>(cb, hw, hb, out);
}